// round 10
// baseline (speedup 1.0000x reference)
#include <cuda_runtime.h>
#include <cuda_fp16.h>

#define NQ_MAX 131072
#define E_MAX  2097152
#define FULL 0xffffffffu

// ---------- device scratch (no allocations allowed) ----------
// invariant: g_count is all-zero at kernel_launch entry (zero-initialized, and
// k_scan_a re-zeroes each element right after reading it).
__device__ int   g_count[NQ_MAX];
__device__ int   g_off[NQ_MAX + 1];
__device__ int   g_cursor[NQ_MAX];
__device__ int   g_bsum[1024];
__device__ __align__(16) float g_sq[NQ_MAX];   // q.u + C (C folded in)
__device__ __align__(16) float g_sk[NQ_MAX];   // kv.v
__device__ __align__(16) int   g_ki[E_MAX];    // sorted key index
__device__ __align__(16) unsigned int g_kph[(size_t)NQ_MAX * 32];  // kv_proj fp16 (half2 per word)

// ---------- kernels ----------
// degree histogram over qi, 8 edges per thread (g_count starts zero: invariant)
__global__ void k_edge1(const int* __restrict__ eidx, int E) {
    int j8 = (blockIdx.x * blockDim.x + threadIdx.x) * 8;
    if (j8 + 7 < E) {
        int4 a = *(const int4*)(eidx + j8);
        int4 b = *(const int4*)(eidx + j8 + 4);
        atomicAdd(&g_count[a.x], 1);
        atomicAdd(&g_count[a.y], 1);
        atomicAdd(&g_count[a.z], 1);
        atomicAdd(&g_count[a.w], 1);
        atomicAdd(&g_count[b.x], 1);
        atomicAdd(&g_count[b.y], 1);
        atomicAdd(&g_count[b.z], 1);
        atomicAdd(&g_count[b.w], 1);
    } else {
        for (int j = j8; j < E; j++) atomicAdd(&g_count[eidx[j]], 1);
    }
}

// block-level exclusive scan -> g_off (block-local), g_bsum; restores g_count=0
__global__ void k_scan_a(int Nq) {
    __shared__ int wsum[32];
    int tid  = threadIdx.x;
    int lane = tid & 31;
    int wid  = tid >> 5;
    int i = blockIdx.x * 1024 + tid;
    int x = 0;
    if (i < Nq) { x = g_count[i]; g_count[i] = 0; }   // read + restore invariant
    int v = x;
    #pragma unroll
    for (int o = 1; o < 32; o <<= 1) {
        int t = __shfl_up_sync(FULL, v, o);
        if (lane >= o) v += t;
    }
    if (lane == 31) wsum[wid] = v;
    __syncthreads();
    if (wid == 0) {
        int w = wsum[lane];
        #pragma unroll
        for (int o = 1; o < 32; o <<= 1) {
            int t = __shfl_up_sync(FULL, w, o);
            if (lane >= o) w += t;
        }
        wsum[lane] = w;
    }
    __syncthreads();
    int incl = v + (wid ? wsum[wid - 1] : 0);
    if (i < Nq) g_off[i] = incl - x;
    if (tid == 1023) g_bsum[blockIdx.x] = incl;
}

// fused: scan g_bsum (per-block recompute, nb <= 1024) + add to offsets + init cursor
__global__ void k_scan_c(int Nq, int E, int nb) {
    __shared__ int spref[1024];
    int tid = threadIdx.x;       // 256 threads
    for (int t = tid; t < nb; t += 256) spref[t] = g_bsum[t];
    __syncthreads();
    for (int off = 1; off < nb; off <<= 1) {
        int t0 = (tid < nb && tid >= off) ? spref[tid - off] : 0;
        int t1 = (256 + tid < nb && 256 + tid >= off) ? spref[256 + tid - off] : 0;
        int t2 = (512 + tid < nb && 512 + tid >= off) ? spref[512 + tid - off] : 0;
        int t3 = (768 + tid < nb && 768 + tid >= off) ? spref[768 + tid - off] : 0;
        __syncthreads();
        if (tid < nb) spref[tid] += t0;
        if (256 + tid < nb) spref[256 + tid] += t1;
        if (512 + tid < nb) spref[512 + tid] += t2;
        if (768 + tid < nb) spref[768 + tid] += t3;
        __syncthreads();
    }
    int i = blockIdx.x * blockDim.x + tid;
    if (i < Nq) {
        int b = i >> 10;
        int off = g_off[i] + (b ? spref[b - 1] : 0);
        g_off[i] = off;
        g_cursor[i] = off;
    }
    if (i == 0) g_off[Nq] = E;
}

// kv_proj = kv @ W^T + b, fp16 output (64-row tile, 4 rows x 4 cols per thread)
// fused: g_sk = kv . v (v computed per block from Wts). Profiled slot: idx 3.
__global__ void k_gemm(const float* __restrict__ x, const float* __restrict__ W,
                       const float* __restrict__ b, const float* __restrict__ aw,
                       int Nk) {
    __shared__ __align__(16) float Wts[64 * 64];  // Wts[j*64+i] = W[i*64+j]
    __shared__ __align__(16) float xs[64 * 68];   // padded stride 68 (bank-safe)
    __shared__ __align__(16) float vs[64];
    int tid = threadIdx.x;
    for (int t = tid * 4; t < 4096; t += 1024) {
        float4 w = *(const float4*)(W + t);
        int i = t >> 6, j = t & 63;
        Wts[(j + 0) * 64 + i] = w.x;
        Wts[(j + 1) * 64 + i] = w.y;
        Wts[(j + 2) * 64 + i] = w.z;
        Wts[(j + 3) * 64 + i] = w.w;
    }
    __syncthreads();
    if (tid < 64) {   // v_j = sum_i W[i][j]*aw2[i] = row j of Wts . aw2
        float vj = 0.f;
        for (int i = 0; i < 64; i++) vj += Wts[tid * 64 + i] * aw[64 + i];
        vs[tid] = vj;
    }
    __syncthreads();
    int r  = tid >> 4;   // 0..15
    int cg = tid & 15;   // 0..15 -> cols cg*4..cg*4+3
    float4 bias = *(const float4*)(b + cg * 4);
    float4 vv   = *(const float4*)(vs + cg * 4);
    int base = blockIdx.x * 64;
    #pragma unroll
    for (int l = 0; l < 4; l++) {
        int row = base + r + l * 16;
        float4 xv = (row < Nk) ? *(const float4*)(x + (size_t)row * 64 + cg * 4)
                               : make_float4(0.f, 0.f, 0.f, 0.f);
        *(float4*)(xs + (r + l * 16) * 68 + cg * 4) = xv;
        float p = xv.x * vv.x + xv.y * vv.y + xv.z * vv.z + xv.w * vv.w;
        #pragma unroll
        for (int o = 8; o; o >>= 1) p += __shfl_xor_sync(FULL, p, o);
        if (cg == 0 && row < Nk) g_sk[row] = p;
    }
    __syncthreads();
    float4 a0 = bias, a1 = bias, a2 = bias, a3 = bias;
    #pragma unroll
    for (int j = 0; j < 64; j++) {
        float4 wv = *(const float4*)(Wts + j * 64 + cg * 4);
        float x0 = xs[(r     ) * 68 + j];
        float x1 = xs[(r + 16) * 68 + j];
        float x2 = xs[(r + 32) * 68 + j];
        float x3 = xs[(r + 48) * 68 + j];
        a0.x += x0 * wv.x; a0.y += x0 * wv.y; a0.z += x0 * wv.z; a0.w += x0 * wv.w;
        a1.x += x1 * wv.x; a1.y += x1 * wv.y; a1.z += x1 * wv.z; a1.w += x1 * wv.w;
        a2.x += x2 * wv.x; a2.y += x2 * wv.y; a2.z += x2 * wv.z; a2.w += x2 * wv.w;
        a3.x += x3 * wv.x; a3.y += x3 * wv.y; a3.z += x3 * wv.z; a3.w += x3 * wv.w;
    }
    int row0 = base + r;
    #pragma unroll
    for (int l = 0; l < 4; l++) {
        int row = row0 + l * 16;
        if (row < Nk) {
            float4 a = l == 0 ? a0 : l == 1 ? a1 : l == 2 ? a2 : a3;
            __half2 h0 = __floats2half2_rn(a.x, a.y);
            __half2 h1 = __floats2half2_rn(a.z, a.w);
            uint2 u;
            u.x = *(unsigned int*)&h0;
            u.y = *(unsigned int*)&h1;
            *(uint2*)(g_kph + (size_t)row * 32 + cg * 2) = u;
        }
    }
}

// counting-sort scatter: place ki into qi-contiguous segment (4B payload only).
// 8 edges per thread for MLP on the atomic->store chains.
__global__ void k_scatter(const int* __restrict__ eidx, int E) {
    int j8 = (blockIdx.x * blockDim.x + threadIdx.x) * 8;
    if (j8 + 7 < E) {
        int4 qa = *(const int4*)(eidx + j8);
        int4 qb = *(const int4*)(eidx + j8 + 4);
        int4 ka = *(const int4*)(eidx + E + j8);
        int4 kb = *(const int4*)(eidx + E + j8 + 4);
        int p0 = atomicAdd(&g_cursor[qa.x], 1);
        int p1 = atomicAdd(&g_cursor[qa.y], 1);
        int p2 = atomicAdd(&g_cursor[qa.z], 1);
        int p3 = atomicAdd(&g_cursor[qa.w], 1);
        int p4 = atomicAdd(&g_cursor[qb.x], 1);
        int p5 = atomicAdd(&g_cursor[qb.y], 1);
        int p6 = atomicAdd(&g_cursor[qb.z], 1);
        int p7 = atomicAdd(&g_cursor[qb.w], 1);
        g_ki[p0] = ka.x;
        g_ki[p1] = ka.y;
        g_ki[p2] = ka.z;
        g_ki[p3] = ka.w;
        g_ki[p4] = kb.x;
        g_ki[p5] = kb.y;
        g_ki[p6] = kb.z;
        g_ki[p7] = kb.w;
    } else {
        for (int j = j8; j < E; j++) {
            int pos = atomicAdd(&g_cursor[eidx[j]], 1);
            g_ki[pos] = eidx[E + j];
        }
    }
}

// g_sq = q.u + C. u and C computed per block (W is L2-hot, 98 blocks only).
__global__ void k_node_scalars(const float* __restrict__ q, const float* __restrict__ W,
                               const float* __restrict__ pb, const float* __restrict__ aw,
                               const float* __restrict__ ab, int Nq) {
    __shared__ __align__(16) float su[64];
    __shared__ float sC;
    int tid = threadIdx.x;
    if (tid < 64) {
        float uj = 0.f;
        for (int r = 0; r < 64; r++) uj += W[r * 64 + tid] * aw[r];
        su[tid] = uj;
    }
    if (tid == 64) {
        float c = ab[0];
        for (int r = 0; r < 64; r++) c += pb[r] * (aw[r] + aw[64 + r]);
        sC = c;
    }
    __syncthreads();
    int lane = tid & 31;
    int warp = blockIdx.x * (blockDim.x >> 5) + (tid >> 5);
    int nwarps = gridDim.x * (blockDim.x >> 5);
    float2 b = *(const float2*)(su + lane * 2);
    for (int w = warp; w < Nq; w += nwarps) {
        float2 a = *(const float2*)(q + (size_t)w * 64 + lane * 2);
        float acc = a.x * b.x + a.y * b.y;
        #pragma unroll
        for (int o = 16; o; o >>= 1) acc += __shfl_xor_sync(FULL, acc, o);
        if (lane == 0) g_sq[w] = acc + sC;
    }
}

// warp per query node: lane i computes ex = exp(leaky(sq + sk[ki])) for its edge,
// then shfl-broadcast + half2 gathers (fp16 kv_proj: half the L2 bytes).
__global__ void k_agg(float* __restrict__ out, int Nq) {
    int w = (blockIdx.x * blockDim.x + threadIdx.x) >> 5;
    int lane = threadIdx.x & 31;
    if (w >= Nq) return;
    int s = g_off[w], e = g_off[w + 1];
    float sqc = g_sq[w];   // includes +C
    const __half2* kp_l = (const __half2*)g_kph + lane;   // row k at kp_l[k*32]
    float sum = 0.f, ax = 0.f, ay = 0.f;
    for (int base = s; base < e; base += 32) {
        int i = base + lane;
        float ex = 0.f; int kn = 0;
        if (i < e) {
            kn = g_ki[i];
            float ev = sqc + g_sk[kn];
            ev = ev > 0.f ? ev : 0.2f * ev;      // leaky relu, alpha 0.2
            ex = __expf(ev);
        }
        sum += ex;
        int cnt = min(32, e - base);
        int j = 0;
        for (; j + 3 < cnt; j += 4) {
            float e0 = __shfl_sync(FULL, ex, j);
            float e1 = __shfl_sync(FULL, ex, j + 1);
            float e2 = __shfl_sync(FULL, ex, j + 2);
            float e3 = __shfl_sync(FULL, ex, j + 3);
            int   k0 = __shfl_sync(FULL, kn, j);
            int   k1 = __shfl_sync(FULL, kn, j + 1);
            int   k2 = __shfl_sync(FULL, kn, j + 2);
            int   k3 = __shfl_sync(FULL, kn, j + 3);
            float2 v0 = __half22float2(kp_l[(size_t)k0 * 32]);
            float2 v1 = __half22float2(kp_l[(size_t)k1 * 32]);
            float2 v2 = __half22float2(kp_l[(size_t)k2 * 32]);
            float2 v3 = __half22float2(kp_l[(size_t)k3 * 32]);
            ax += e0 * v0.x; ay += e0 * v0.y;
            ax += e1 * v1.x; ay += e1 * v1.y;
            ax += e2 * v2.x; ay += e2 * v2.y;
            ax += e3 * v3.x; ay += e3 * v3.y;
        }
        for (; j < cnt; j++) {
            float e0 = __shfl_sync(FULL, ex, j);
            int   k0 = __shfl_sync(FULL, kn, j);
            float2 v0 = __half22float2(kp_l[(size_t)k0 * 32]);
            ax += e0 * v0.x; ay += e0 * v0.y;
        }
    }
    #pragma unroll
    for (int o = 16; o; o >>= 1) sum += __shfl_xor_sync(FULL, sum, o);
    float inv = 1.0f / (sum + 1e-10f);   // EPS from reference
    *(float2*)(out + (size_t)w * 64 + lane * 2) = make_float2(ax * inv, ay * inv);
}

// ---------- launch ----------
extern "C" void kernel_launch(void* const* d_in, const int* in_sizes, int n_in,
                              void* d_out, int out_size) {
    const float* q  = (const float*)d_in[0];      // query_nodes (Nq,64)
    const float* kv = (const float*)d_in[1];      // key_value_nodes (Nk,64)
    const int*   ei = (const int*)d_in[2];        // edge_index (2,E) int32
    const float* W  = (const float*)d_in[3];      // proj_w (64,64)
    const float* pb = (const float*)d_in[4];      // proj_b (64)
    const float* aw = (const float*)d_in[5];      // attend_w (1,128)
    const float* ab = (const float*)d_in[6];      // attend_b (1)
    float* out = (float*)d_out;

    int Nq = in_sizes[0] / 64;
    int Nk = in_sizes[1] / 64;
    int E  = in_sizes[2] / 2;
    int nb = (Nq + 1023) / 1024;

    k_edge1<<<(E / 8 + 255) / 256, 256>>>(ei, E);                 // idx 0
    k_scan_a<<<nb, 1024>>>(Nq);                                   // idx 1
    k_scan_c<<<(Nq + 255) / 256, 256>>>(Nq, E, nb);               // idx 2
    k_gemm<<<(Nk + 63) / 64, 256>>>(kv, W, pb, aw, Nk);           // idx 3 (profiled)
    k_scatter<<<(E / 8 + 255) / 256, 256>>>(ei, E);               // idx 4
    k_node_scalars<<<98, 1024>>>(q, W, pb, aw, ab, Nq);           // idx 5
    k_agg<<<(Nq + 7) / 8, 256>>>(out, Nq);                        // idx 6
}

// round 12
// speedup vs baseline: 1.1740x; 1.1740x over previous
#include <cuda_runtime.h>
#include <cuda_fp16.h>

#define NQ_MAX 131072
#define E_MAX  2097152
#define FULL 0xffffffffu

// ---------- device scratch (no allocations allowed) ----------
// invariant: g_count is all-zero at kernel_launch entry (zero-initialized, and
// k_scan_a re-zeroes each element right after reading it).
__device__ int   g_count[NQ_MAX];
__device__ int   g_off[NQ_MAX + 1];
__device__ int   g_cursor[NQ_MAX];
__device__ int   g_bsum[1024];
__device__ __align__(16) float g_sq[NQ_MAX];   // q.u + pb.wq + ab (all q-side consts folded)
__device__ __align__(16) float g_sk[NQ_MAX];   // kp_row . wk  (bias included via accum)
__device__ __align__(16) int   g_ki[E_MAX];    // sorted key index
__device__ __align__(16) unsigned int g_kph[(size_t)NQ_MAX * 32];  // kv_proj fp16 (half2 words)

// ---------- kernels ----------
// degree histogram over qi, 4 edges per thread (R9-proven)
__global__ void k_edge1(const int* __restrict__ eidx, int E) {
    int j4 = (blockIdx.x * blockDim.x + threadIdx.x) * 4;
    if (j4 + 3 < E) {
        int4 v = *(const int4*)(eidx + j4);
        atomicAdd(&g_count[v.x], 1);
        atomicAdd(&g_count[v.y], 1);
        atomicAdd(&g_count[v.z], 1);
        atomicAdd(&g_count[v.w], 1);
    } else {
        for (int j = j4; j < E; j++) atomicAdd(&g_count[eidx[j]], 1);
    }
}

// block-level exclusive scan -> g_off (block-local), g_bsum; restores g_count=0
__global__ void k_scan_a(int Nq) {
    __shared__ int wsum[32];
    int tid  = threadIdx.x;
    int lane = tid & 31;
    int wid  = tid >> 5;
    int i = blockIdx.x * 1024 + tid;
    int x = 0;
    if (i < Nq) { x = g_count[i]; g_count[i] = 0; }
    int v = x;
    #pragma unroll
    for (int o = 1; o < 32; o <<= 1) {
        int t = __shfl_up_sync(FULL, v, o);
        if (lane >= o) v += t;
    }
    if (lane == 31) wsum[wid] = v;
    __syncthreads();
    if (wid == 0) {
        int w = wsum[lane];
        #pragma unroll
        for (int o = 1; o < 32; o <<= 1) {
            int t = __shfl_up_sync(FULL, w, o);
            if (lane >= o) w += t;
        }
        wsum[lane] = w;
    }
    __syncthreads();
    int incl = v + (wid ? wsum[wid - 1] : 0);
    if (i < Nq) g_off[i] = incl - x;
    if (tid == 1023) g_bsum[blockIdx.x] = incl;
}

// fused: scan g_bsum (per-block recompute, nb <= 1024) + add to offsets + init cursor
__global__ void k_scan_c(int Nq, int E, int nb) {
    __shared__ int spref[1024];
    int tid = threadIdx.x;       // 256 threads
    for (int t = tid; t < nb; t += 256) spref[t] = g_bsum[t];
    __syncthreads();
    for (int off = 1; off < nb; off <<= 1) {
        int t0 = (tid < nb && tid >= off) ? spref[tid - off] : 0;
        int t1 = (256 + tid < nb && 256 + tid >= off) ? spref[256 + tid - off] : 0;
        int t2 = (512 + tid < nb && 512 + tid >= off) ? spref[512 + tid - off] : 0;
        int t3 = (768 + tid < nb && 768 + tid >= off) ? spref[768 + tid - off] : 0;
        __syncthreads();
        if (tid < nb) spref[tid] += t0;
        if (256 + tid < nb) spref[256 + tid] += t1;
        if (512 + tid < nb) spref[512 + tid] += t2;
        if (768 + tid < nb) spref[768 + tid] += t3;
        __syncthreads();
    }
    int i = blockIdx.x * blockDim.x + tid;
    if (i < Nq) {
        int b = i >> 10;
        int off = g_off[i] + (b ? spref[b - 1] : 0);
        g_off[i] = off;
        g_cursor[i] = off;
    }
    if (i == 0) g_off[Nq] = E;
}

// kv_proj = kv @ W^T + b, fp16 out. 64-row tile, 128 threads, thread = 4 rows x 8 cols
// (cols cg*4..+3 and cg*4+32..+35 -> conflict-free W LDS.128s; x reads broadcast).
// 1.5 B/FMA shared traffic. Fused: g_sk[row] = kp_row . wk from fp32 accumulators.
__global__ void __launch_bounds__(128) k_gemm(
        const float* __restrict__ x, const float* __restrict__ W,
        const float* __restrict__ b, const float* __restrict__ aw, int Nk) {
    __shared__ __align__(16) float Wts[64 * 64];  // Wts[j*64+i] = W[i*64+j]
    __shared__ __align__(16) float xs[64 * 68];   // row-major, stride 68
    int tid = threadIdx.x;   // 128
    for (int t = tid * 4; t < 4096; t += 512) {
        float4 w = *(const float4*)(W + t);
        int i = t >> 6, j = t & 63;
        Wts[(j + 0) * 64 + i] = w.x;
        Wts[(j + 1) * 64 + i] = w.y;
        Wts[(j + 2) * 64 + i] = w.z;
        Wts[(j + 3) * 64 + i] = w.w;
    }
    int base = blockIdx.x * 64;
    {
        int lr = tid >> 4;   // 0..7
        int lj = tid & 15;   // 0..15
        #pragma unroll
        for (int it = 0; it < 8; it++) {
            int row = it * 8 + lr;
            int grow = base + row;
            float4 xv = (grow < Nk) ? *(const float4*)(x + (size_t)grow * 64 + lj * 4)
                                    : make_float4(0.f, 0.f, 0.f, 0.f);
            *(float4*)(xs + row * 68 + lj * 4) = xv;
        }
    }
    __syncthreads();
    int rg = tid >> 3;   // 0..15 -> rows rg, rg+16, rg+32, rg+48
    int cg = tid & 7;    // 0..7  -> cols cg*4..+3 and cg*4+32..+35
    int c0 = cg * 4, c1 = cg * 4 + 32;
    float4 b0 = *(const float4*)(b + c0);
    float4 b1 = *(const float4*)(b + c1);
    float4 acc0[4], acc1[4];
    #pragma unroll
    for (int l = 0; l < 4; l++) { acc0[l] = b0; acc1[l] = b1; }
    #pragma unroll
    for (int j = 0; j < 64; j++) {
        float4 w0 = *(const float4*)(Wts + j * 64 + c0);
        float4 w1 = *(const float4*)(Wts + j * 64 + c1);
        float xv0 = xs[(rg     ) * 68 + j];
        float xv1 = xs[(rg + 16) * 68 + j];
        float xv2 = xs[(rg + 32) * 68 + j];
        float xv3 = xs[(rg + 48) * 68 + j];
        acc0[0].x += xv0 * w0.x; acc0[0].y += xv0 * w0.y; acc0[0].z += xv0 * w0.z; acc0[0].w += xv0 * w0.w;
        acc1[0].x += xv0 * w1.x; acc1[0].y += xv0 * w1.y; acc1[0].z += xv0 * w1.z; acc1[0].w += xv0 * w1.w;
        acc0[1].x += xv1 * w0.x; acc0[1].y += xv1 * w0.y; acc0[1].z += xv1 * w0.z; acc0[1].w += xv1 * w0.w;
        acc1[1].x += xv1 * w1.x; acc1[1].y += xv1 * w1.y; acc1[1].z += xv1 * w1.z; acc1[1].w += xv1 * w1.w;
        acc0[2].x += xv2 * w0.x; acc0[2].y += xv2 * w0.y; acc0[2].z += xv2 * w0.z; acc0[2].w += xv2 * w0.w;
        acc1[2].x += xv2 * w1.x; acc1[2].y += xv2 * w1.y; acc1[2].z += xv2 * w1.z; acc1[2].w += xv2 * w1.w;
        acc0[3].x += xv3 * w0.x; acc0[3].y += xv3 * w0.y; acc0[3].z += xv3 * w0.z; acc0[3].w += xv3 * w0.w;
        acc1[3].x += xv3 * w1.x; acc1[3].y += xv3 * w1.y; acc1[3].z += xv3 * w1.z; acc1[3].w += xv3 * w1.w;
    }
    // fused sk = kp_row . wk (reduce over the 8 cg threads, consecutive lanes)
    float4 a0 = *(const float4*)(aw + 64 + c0);
    float4 a1 = *(const float4*)(aw + 64 + c1);
    #pragma unroll
    for (int l = 0; l < 4; l++) {
        float p = acc0[l].x * a0.x + acc0[l].y * a0.y + acc0[l].z * a0.z + acc0[l].w * a0.w
                + acc1[l].x * a1.x + acc1[l].y * a1.y + acc1[l].z * a1.z + acc1[l].w * a1.w;
        p += __shfl_xor_sync(FULL, p, 1);
        p += __shfl_xor_sync(FULL, p, 2);
        p += __shfl_xor_sync(FULL, p, 4);
        int grow = base + rg + l * 16;
        if (cg == 0 && grow < Nk) g_sk[grow] = p;
    }
    // fp16 stores
    #pragma unroll
    for (int l = 0; l < 4; l++) {
        int grow = base + rg + l * 16;
        if (grow < Nk) {
            __half2 h00 = __floats2half2_rn(acc0[l].x, acc0[l].y);
            __half2 h01 = __floats2half2_rn(acc0[l].z, acc0[l].w);
            __half2 h10 = __floats2half2_rn(acc1[l].x, acc1[l].y);
            __half2 h11 = __floats2half2_rn(acc1[l].z, acc1[l].w);
            uint2 u0, u1;
            u0.x = *(unsigned int*)&h00; u0.y = *(unsigned int*)&h01;
            u1.x = *(unsigned int*)&h10; u1.y = *(unsigned int*)&h11;
            *(uint2*)(g_kph + (size_t)grow * 32 + cg * 2)      = u0;
            *(uint2*)(g_kph + (size_t)grow * 32 + cg * 2 + 16) = u1;
        }
    }
}

// counting-sort scatter: place ki into qi-contiguous segment (4B payload).
// 4 edges per thread (R9-proven).
__global__ void k_scatter(const int* __restrict__ eidx, int E) {
    int j4 = (blockIdx.x * blockDim.x + threadIdx.x) * 4;
    if (j4 + 3 < E) {
        int4 qq = *(const int4*)(eidx + j4);
        int4 kk = *(const int4*)(eidx + E + j4);
        int p0 = atomicAdd(&g_cursor[qq.x], 1);
        int p1 = atomicAdd(&g_cursor[qq.y], 1);
        int p2 = atomicAdd(&g_cursor[qq.z], 1);
        int p3 = atomicAdd(&g_cursor[qq.w], 1);
        g_ki[p0] = kk.x;
        g_ki[p1] = kk.y;
        g_ki[p2] = kk.z;
        g_ki[p3] = kk.w;
    } else {
        for (int j = j4; j < E; j++) {
            int pos = atomicAdd(&g_cursor[eidx[j]], 1);
            g_ki[pos] = eidx[E + j];
        }
    }
}

// g_sq = q.u + (pb.wq + ab). u and C computed per block (W is L2-hot, 98 blocks).
__global__ void k_node_scalars(const float* __restrict__ q, const float* __restrict__ W,
                               const float* __restrict__ pb, const float* __restrict__ aw,
                               const float* __restrict__ ab, int Nq) {
    __shared__ __align__(16) float su[64];
    __shared__ float sC;
    int tid = threadIdx.x;
    if (tid < 64) {
        float uj = 0.f;
        for (int r = 0; r < 64; r++) uj += W[r * 64 + tid] * aw[r];
        su[tid] = uj;
    }
    if (tid == 64) {
        float c = ab[0];
        for (int r = 0; r < 64; r++) c += pb[r] * aw[r];   // wq part only (wk in g_sk)
        sC = c;
    }
    __syncthreads();
    int lane = tid & 31;
    int warp = blockIdx.x * (blockDim.x >> 5) + (tid >> 5);
    int nwarps = gridDim.x * (blockDim.x >> 5);
    float2 b = *(const float2*)(su + lane * 2);
    for (int w = warp; w < Nq; w += nwarps) {
        float2 a = *(const float2*)(q + (size_t)w * 64 + lane * 2);
        float acc = a.x * b.x + a.y * b.y;
        #pragma unroll
        for (int o = 16; o; o >>= 1) acc += __shfl_xor_sync(FULL, acc, o);
        if (lane == 0) g_sq[w] = acc + sC;
    }
}

// warp per query node: lane i computes ex = exp(leaky(sq + sk[ki])) for its edge,
// then shfl-broadcast + half2 gathers (fp16 kv_proj: half the L2 bytes).
__global__ void k_agg(float* __restrict__ out, int Nq) {
    int w = (blockIdx.x * blockDim.x + threadIdx.x) >> 5;
    int lane = threadIdx.x & 31;
    if (w >= Nq) return;
    int s = g_off[w], e = g_off[w + 1];
    float sqc = g_sq[w];
    const __half2* kp_l = (const __half2*)g_kph + lane;   // row k at kp_l[k*32]
    float sum = 0.f, ax = 0.f, ay = 0.f;
    for (int base = s; base < e; base += 32) {
        int i = base + lane;
        float ex = 0.f; int kn = 0;
        if (i < e) {
            kn = g_ki[i];
            float ev = sqc + g_sk[kn];
            ev = ev > 0.f ? ev : 0.2f * ev;      // leaky relu, alpha 0.2
            ex = __expf(ev);
        }
        sum += ex;
        int cnt = min(32, e - base);
        int j = 0;
        for (; j + 3 < cnt; j += 4) {
            float e0 = __shfl_sync(FULL, ex, j);
            float e1 = __shfl_sync(FULL, ex, j + 1);
            float e2 = __shfl_sync(FULL, ex, j + 2);
            float e3 = __shfl_sync(FULL, ex, j + 3);
            int   k0 = __shfl_sync(FULL, kn, j);
            int   k1 = __shfl_sync(FULL, kn, j + 1);
            int   k2 = __shfl_sync(FULL, kn, j + 2);
            int   k3 = __shfl_sync(FULL, kn, j + 3);
            float2 v0 = __half22float2(kp_l[(size_t)k0 * 32]);
            float2 v1 = __half22float2(kp_l[(size_t)k1 * 32]);
            float2 v2 = __half22float2(kp_l[(size_t)k2 * 32]);
            float2 v3 = __half22float2(kp_l[(size_t)k3 * 32]);
            ax += e0 * v0.x; ay += e0 * v0.y;
            ax += e1 * v1.x; ay += e1 * v1.y;
            ax += e2 * v2.x; ay += e2 * v2.y;
            ax += e3 * v3.x; ay += e3 * v3.y;
        }
        for (; j < cnt; j++) {
            float e0 = __shfl_sync(FULL, ex, j);
            int   k0 = __shfl_sync(FULL, kn, j);
            float2 v0 = __half22float2(kp_l[(size_t)k0 * 32]);
            ax += e0 * v0.x; ay += e0 * v0.y;
        }
    }
    #pragma unroll
    for (int o = 16; o; o >>= 1) sum += __shfl_xor_sync(FULL, sum, o);
    float inv = 1.0f / (sum + 1e-10f);   // EPS from reference
    *(float2*)(out + (size_t)w * 64 + lane * 2) = make_float2(ax * inv, ay * inv);
}

// ---------- launch ----------
extern "C" void kernel_launch(void* const* d_in, const int* in_sizes, int n_in,
                              void* d_out, int out_size) {
    const float* q  = (const float*)d_in[0];      // query_nodes (Nq,64)
    const float* kv = (const float*)d_in[1];      // key_value_nodes (Nk,64)
    const int*   ei = (const int*)d_in[2];        // edge_index (2,E) int32
    const float* W  = (const float*)d_in[3];      // proj_w (64,64)
    const float* pb = (const float*)d_in[4];      // proj_b (64)
    const float* aw = (const float*)d_in[5];      // attend_w (1,128)
    const float* ab = (const float*)d_in[6];      // attend_b (1)
    float* out = (float*)d_out;

    int Nq = in_sizes[0] / 64;
    int Nk = in_sizes[1] / 64;
    int E  = in_sizes[2] / 2;
    int nb = (Nq + 1023) / 1024;

    k_edge1<<<(E / 4 + 255) / 256, 256>>>(ei, E);                 // idx 0
    k_scan_a<<<nb, 1024>>>(Nq);                                   // idx 1
    k_scan_c<<<(Nq + 255) / 256, 256>>>(Nq, E, nb);               // idx 2
    k_gemm<<<(Nk + 63) / 64, 128>>>(kv, W, pb, aw, Nk);           // idx 3 (profiled)
    k_scatter<<<(E / 4 + 255) / 256, 256>>>(ei, E);               // idx 4
    k_node_scalars<<<98, 1024>>>(q, W, pb, aw, ab, Nq);           // idx 5
    k_agg<<<(Nq + 7) / 8, 256>>>(out, Nq);                        // idx 6
}